// round 17
// baseline (speedup 1.0000x reference)
#include <cuda_runtime.h>
#include <cstdint>
#include <cstddef>

// Problem constants
#define NM 4
#define NB 2048
#define ND 1024
#define NE 8
#define NO 1024
#define NC 2

#define DSPLIT 2       // D split across blocks (512 each)
#define DLOC 512
#define NCHU 16        // chunks of 32 cols
#define CHC 32
#define XSTR 34        // x-tile row stride (floats); mod 32 == 2

// Scratch (no allocations allowed)
__device__ float g_vtab[ND * NE * NC];          // [d][e*2+c]  64 KB
__device__ float g_bdot[NE * NC];
__device__ float g_part[DSPLIT * NM * NB * 24]; // partials [split][tok][24]

// packed f32x2 FMA (sm_100a+)
#define FMA_F32X2(acc, a, b) \
    asm("fma.rn.f32x2 %0, %1, %2, %0;" : "+l"(acc) : "l"(a), "l"(b))
#define BCAST_F32X2(dst, f) \
    asm("mov.b64 %0, {%1, %1};" : "=l"(dst) : "f"(f))
#define UNPACK_F32X2(lo, hi, in) \
    asm("mov.b64 {%0, %1}, %2;" : "=f"(lo), "=f"(hi) : "l"(in))

// ---------------------------------------------------------------------------
// Pass A (proven, ~4.2us timed): V = expert_w @ head_w, + bdot fused.
// ---------------------------------------------------------------------------
__global__ void __launch_bounds__(256) build_vtab_kernel(
    const float* __restrict__ expert_w,
    const float* __restrict__ head_w,
    const float* __restrict__ expert_b)
{
    __shared__ float hw[NO * NC];
    for (int i = threadIdx.x; i < NO * NC; i += 256) hw[i] = head_w[i];
    __syncthreads();

    const int lane = threadIdx.x & 31;
    const int wid  = threadIdx.x >> 5;
    const int r    = (blockIdx.x << 3) + wid;

    const float4* row4 = (const float4*)(expert_w + ((size_t)r << 10));
    float4 w[8];
#pragma unroll
    for (int i = 0; i < 8; i++) w[i] = row4[i * 32 + lane];

    float a0 = 0.f, a1 = 0.f;
#pragma unroll
    for (int i = 0; i < 8; i++) {
        const float4* h = (const float4*)(hw + ((i * 128 + lane * 4) << 1));
        float4 h0 = h[0], h1 = h[1];
        a0 += w[i].x * h0.x + w[i].y * h0.z + w[i].z * h1.x + w[i].w * h1.z;
        a1 += w[i].x * h0.y + w[i].y * h0.w + w[i].z * h1.y + w[i].w * h1.w;
    }
#pragma unroll
    for (int off = 16; off; off >>= 1) {
        a0 += __shfl_down_sync(0xffffffffu, a0, off);
        a1 += __shfl_down_sync(0xffffffffu, a1, off);
    }
    if (lane == 0) {
        int e = r >> 10, d = r & 1023;
        g_vtab[(d << 4) + (e << 1) + 0] = a0;
        g_vtab[(d << 4) + (e << 1) + 1] = a1;
    }

    if (blockIdx.x < 8 && wid == 0) {
        int e = blockIdx.x;
        const float4* eb4 = ((const float4*)expert_b) + (e << 8);
        float b0 = 0.f, b1 = 0.f;
#pragma unroll
        for (int i = 0; i < 8; i++) {
            float4 bb = eb4[i * 32 + lane];
            const float4* h = (const float4*)(hw + ((i * 32 + lane) << 3));
            float4 h0 = h[0], h1 = h[1];
            b0 += bb.x * h0.x + bb.y * h0.z + bb.z * h1.x + bb.w * h1.z;
            b1 += bb.x * h0.y + bb.y * h0.w + bb.z * h1.y + bb.w * h1.w;
        }
#pragma unroll
        for (int off = 16; off; off >>= 1) {
            b0 += __shfl_down_sync(0xffffffffu, b0, off);
            b1 += __shfl_down_sync(0xffffffffu, b1, off);
        }
        if (lane == 0) { g_bdot[e * 2] = b0; g_bdot[e * 2 + 1] = b1; }
    }
}

// ---------------------------------------------------------------------------
// Main pass, round 17: CLEAN occupancy experiment. Same verified math
// (2 tokens/thread, 6 broadcast LDS.128 + 24 FFMA2 per d), footprint cut to
// 57.8 KB (DSPLIT=2 table slice 48 KB + 32-col x tile 8.7 KB) so THREE
// blocks fit per SM = 24 warps (was 16). launch_bounds(256,3) = 84-reg cap;
// inner loop register-dieted (per-d compute blocks).
// Grid 256 = 128 token-groups x 2 d-splits; single wave on 444 slots.
// ---------------------------------------------------------------------------
__global__ void __launch_bounds__(256, 3) moe_main_kernel(
    const float* __restrict__ x,
    const float* __restrict__ gate_w)
{
    extern __shared__ float sm[];
    float* gt = sm;                     // 4096 floats: gate slice [512][8]
    float* vt = sm + 4096;              // 8192 floats: V slice [512][16]
    float* xs = sm + 12288;             // 64*34 = 2176 floats
    float* rr = sm;                     // fold buffer alias (all dead)

    const int tid = threadIdx.x;
    const int tg  = blockIdx.x >> 1;    // token group 0..127
    const int ds  = blockIdx.x & 1;     // d-split
    const int b0  = tg << 4;            // 16 b-values (64 tokens)
    const int dof = ds * DLOC;
    const int t   = tid & 31;           // token lane (A=t, B=t+32)
    const int s   = tid >> 3 >> 2;      // == tid>>5: d-slice 0..7

    // ---- fill table slices (coalesced float4) ----
    {
        const float4* gsrc = (const float4*)gate_w;   // [d][8] = 2 f4/row
        for (int i = tid; i < 1024; i += 256) {
            int d = i >> 1, h = i & 1;
            *(float4*)(gt + (d << 3) + (h << 2)) = gsrc[((dof + d) << 1) + h];
        }
        const float4* vsrc = (const float4*)g_vtab;   // [d][16] = 4 f4/row
        for (int i = tid; i < 2048; i += 256) {
            int d = i >> 2, q = i & 3;
            *(float4*)(vt + (d << 4) + (q << 2)) = vsrc[((dof + d) << 2) + q];
        }
    }

    unsigned long long gaA[4], vaA[8], gaB[4], vaB[8];
#pragma unroll
    for (int k = 0; k < 4; k++) { gaA[k] = 0ull; gaB[k] = 0ull; }
#pragma unroll
    for (int k = 0; k < 8; k++) { vaA[k] = 0ull; vaB[k] = 0ull; }

    // staging geometry: 2 float4 per thread per chunk (64 rows x 8 f4)
    const int r0 = tid >> 3,           c0 = tid & 7;
    const int r1 = (tid + 256) >> 3,   c1 = tid & 7;
    const int grow0 = ((r0 & 3) << 11) + b0 + (r0 >> 2);
    const int grow1 = ((r1 & 3) << 11) + b0 + (r1 >> 2);

    for (int ch = 0; ch < NCHU; ch++) {
        const int dc = dof + (ch << 5);
        __syncthreads();   // xs reusable (and table fill done, iter 0)
        {
            float4 v0 = *(const float4*)(x + ((size_t)grow0 << 10) + dc + (c0 << 2));
            float4 v1 = *(const float4*)(x + ((size_t)grow1 << 10) + dc + (c1 << 2));
            float* d0 = xs + r0 * XSTR + (c0 << 2);
            float* d1 = xs + r1 * XSTR + (c1 << 2);
            *(float2*)(d0)     = make_float2(v0.x, v0.y);
            *(float2*)(d0 + 2) = make_float2(v0.z, v0.w);
            *(float2*)(d1)     = make_float2(v1.x, v1.y);
            *(float2*)(d1 + 2) = make_float2(v1.z, v1.w);
        }
        __syncthreads();

        const float* xA = xs + t * XSTR + (s << 2);
        const float* xB = xA + 32 * XSTR;
        const int dl0 = (ch << 5) + (s << 2);     // local d base (0..511)
#pragma unroll
        for (int j = 0; j < 4; j += 2) {
            float2 xa = *(const float2*)(xA + j);
            float2 xb = *(const float2*)(xB + j);
            const int dl = dl0 + j;
            // ---- d = dl ----
            {
                unsigned long long a0, bp0;
                BCAST_F32X2(a0, xa.x); BCAST_F32X2(bp0, xb.x);
                const ulonglong2* gp = (const ulonglong2*)(gt + (dl << 3));
                ulonglong2 g0 = gp[0], g1 = gp[1];
                FMA_F32X2(gaA[0], a0, g0.x); FMA_F32X2(gaA[1], a0, g0.y);
                FMA_F32X2(gaA[2], a0, g1.x); FMA_F32X2(gaA[3], a0, g1.y);
                FMA_F32X2(gaB[0], bp0, g0.x); FMA_F32X2(gaB[1], bp0, g0.y);
                FMA_F32X2(gaB[2], bp0, g1.x); FMA_F32X2(gaB[3], bp0, g1.y);
                const ulonglong2* vp = (const ulonglong2*)(vt + (dl << 4));
                ulonglong2 v0 = vp[0], v1 = vp[1], v2 = vp[2], v3 = vp[3];
                FMA_F32X2(vaA[0], a0, v0.x); FMA_F32X2(vaA[1], a0, v0.y);
                FMA_F32X2(vaA[2], a0, v1.x); FMA_F32X2(vaA[3], a0, v1.y);
                FMA_F32X2(vaA[4], a0, v2.x); FMA_F32X2(vaA[5], a0, v2.y);
                FMA_F32X2(vaA[6], a0, v3.x); FMA_F32X2(vaA[7], a0, v3.y);
                FMA_F32X2(vaB[0], bp0, v0.x); FMA_F32X2(vaB[1], bp0, v0.y);
                FMA_F32X2(vaB[2], bp0, v1.x); FMA_F32X2(vaB[3], bp0, v1.y);
                FMA_F32X2(vaB[4], bp0, v2.x); FMA_F32X2(vaB[5], bp0, v2.y);
                FMA_F32X2(vaB[6], bp0, v3.x); FMA_F32X2(vaB[7], bp0, v3.y);
            }
            // ---- d = dl + 1 ----
            {
                unsigned long long a1, bp1;
                BCAST_F32X2(a1, xa.y); BCAST_F32X2(bp1, xb.y);
                const ulonglong2* gp = (const ulonglong2*)(gt + ((dl + 1) << 3));
                ulonglong2 g2 = gp[0], g3 = gp[1];
                FMA_F32X2(gaA[0], a1, g2.x); FMA_F32X2(gaA[1], a1, g2.y);
                FMA_F32X2(gaA[2], a1, g3.x); FMA_F32X2(gaA[3], a1, g3.y);
                FMA_F32X2(gaB[0], bp1, g2.x); FMA_F32X2(gaB[1], bp1, g2.y);
                FMA_F32X2(gaB[2], bp1, g3.x); FMA_F32X2(gaB[3], bp1, g3.y);
                const ulonglong2* vp = (const ulonglong2*)(vt + ((dl + 1) << 4));
                ulonglong2 v4 = vp[0], v5 = vp[1], v6 = vp[2], v7 = vp[3];
                FMA_F32X2(vaA[0], a1, v4.x); FMA_F32X2(vaA[1], a1, v4.y);
                FMA_F32X2(vaA[2], a1, v5.x); FMA_F32X2(vaA[3], a1, v5.y);
                FMA_F32X2(vaA[4], a1, v6.x); FMA_F32X2(vaA[5], a1, v6.y);
                FMA_F32X2(vaA[6], a1, v7.x); FMA_F32X2(vaA[7], a1, v7.y);
                FMA_F32X2(vaB[0], bp1, v4.x); FMA_F32X2(vaB[1], bp1, v4.y);
                FMA_F32X2(vaB[2], bp1, v5.x); FMA_F32X2(vaB[3], bp1, v5.y);
                FMA_F32X2(vaB[4], bp1, v6.x); FMA_F32X2(vaB[5], bp1, v6.y);
                FMA_F32X2(vaB[6], bp1, v7.x); FMA_F32X2(vaB[7], bp1, v7.y);
            }
        }
    }

    // ---- fold 8 slices via smem (rr aliases tables + xs, all dead) ----
    __syncthreads();
    {
        float* rp = rr + (s * 32 + t) * 49;
#pragma unroll
        for (int k = 0; k < 4; k++) UNPACK_F32X2(rp[2 * k],      rp[2 * k + 1],  gaA[k]);
#pragma unroll
        for (int k = 0; k < 8; k++) UNPACK_F32X2(rp[8 + 2 * k],  rp[9 + 2 * k],  vaA[k]);
#pragma unroll
        for (int k = 0; k < 4; k++) UNPACK_F32X2(rp[24 + 2 * k], rp[25 + 2 * k], gaB[k]);
#pragma unroll
        for (int k = 0; k < 8; k++) UNPACK_F32X2(rp[32 + 2 * k], rp[33 + 2 * k], vaB[k]);
    }
    __syncthreads();

    if (tid < 64) {
        const int q   = tid;                 // token 0..63
        const int lt  = q & 31;
        const int off = (q >> 5) * 24;
        float c[24];
#pragma unroll
        for (int k = 0; k < 24; k++) c[k] = rr[lt * 49 + off + k];
#pragma unroll
        for (int s2 = 1; s2 < 8; s2++) {
            const float* rp = rr + (s2 * 32 + lt) * 49 + off;
#pragma unroll
            for (int k = 0; k < 24; k++) c[k] += rp[k];
        }
        int tok = ((q & 3) << 11) + b0 + (q >> 2);      // m*2048 + b
        float4* pp = (float4*)(g_part + ((size_t)ds * NM * NB + tok) * 24);
#pragma unroll
        for (int k = 0; k < 6; k++)
            pp[k] = make_float4(c[4 * k], c[4 * k + 1], c[4 * k + 2], c[4 * k + 3]);
    }
}

// ---------------------------------------------------------------------------
// Reduce (proven round-8/12): sum splits, winner, m-mean, head bias.
// ---------------------------------------------------------------------------
__global__ void __launch_bounds__(256) reduce_kernel(
    const float* __restrict__ gate_b,
    const float* __restrict__ head_b,
    float* __restrict__ out)
{
    const int gt = blockIdx.x * 256 + threadIdx.x;   // 0..8191
    const int b  = gt >> 2;
    const int m  = gt & 3;
    const int tok = (m << 11) + b;

    float c[24];
    {
        const float4* p0 = (const float4*)(g_part + (size_t)tok * 24);
#pragma unroll
        for (int k = 0; k < 6; k++) {
            float4 v = p0[k];
            c[4 * k] = v.x; c[4 * k + 1] = v.y; c[4 * k + 2] = v.z; c[4 * k + 3] = v.w;
        }
#pragma unroll
        for (int sp = 1; sp < DSPLIT; sp++) {
            const float4* pp = (const float4*)(g_part + ((size_t)sp * NM * NB + tok) * 24);
#pragma unroll
            for (int k = 0; k < 6; k++) {
                float4 v = pp[k];
                c[4 * k]     += v.x; c[4 * k + 1] += v.y;
                c[4 * k + 2] += v.z; c[4 * k + 3] += v.w;
            }
        }
    }

    float g[8];
#pragma unroll
    for (int e = 0; e < 8; e++) g[e] = c[e] + gate_b[e];
    int i1 = 0; float m1 = g[0];
#pragma unroll
    for (int e = 1; e < 8; e++) if (g[e] > m1) { m1 = g[e]; i1 = e; }
    int i2 = 0; float m2 = -3.402823466e38f;
#pragma unroll
    for (int e = 0; e < 8; e++) if (e != i1 && g[e] > m2) { m2 = g[e]; i2 = e; }
    int w = (i1 > i2) ? i1 : i2;

    float o0 = c[8 + (w << 1) + 0] + g_bdot[(w << 1) + 0];
    float o1 = c[8 + (w << 1) + 1] + g_bdot[(w << 1) + 1];

    o0 += __shfl_down_sync(0xffffffffu, o0, 2);
    o0 += __shfl_down_sync(0xffffffffu, o0, 1);
    o1 += __shfl_down_sync(0xffffffffu, o1, 2);
    o1 += __shfl_down_sync(0xffffffffu, o1, 1);

    if (m == 0) {
        out[(b << 1) + 0] = 0.25f * o0 + head_b[0];
        out[(b << 1) + 1] = 0.25f * o1 + head_b[1];
    }
}

// ---------------------------------------------------------------------------
extern "C" void kernel_launch(void* const* d_in, const int* in_sizes, int n_in,
                              void* d_out, int out_size)
{
    const float* x        = (const float*)d_in[0];
    const float* gate_w   = (const float*)d_in[1];
    const float* gate_b   = (const float*)d_in[2];
    const float* expert_w = (const float*)d_in[3];
    const float* expert_b = (const float*)d_in[4];
    const float* head_w   = (const float*)d_in[5];
    const float* head_b   = (const float*)d_in[6];
    float* out = (float*)d_out;

    const size_t SMEM = (12288 + 64 * XSTR) * sizeof(float);   // 57,856 B
    cudaFuncSetAttribute(moe_main_kernel,
                         cudaFuncAttributeMaxDynamicSharedMemorySize, (int)SMEM);

    build_vtab_kernel<<<1024, 256>>>(expert_w, head_w, expert_b);
    moe_main_kernel<<<256, 256, SMEM>>>(x, gate_w);
    reduce_kernel<<<32, 256>>>(gate_b, head_b, out);
}